// round 13
// baseline (speedup 1.0000x reference)
#include <cuda_runtime.h>
#include <cstdint>

// Fused GRU cell — bf16 hi/lo split (3 MMAs), mma.sync + ldmatrix(A only),
// B operands pre-arranged in GLOBAL scratch in mma-fragment order and loaded
// straight to registers with LDG.128 (no smem round trip for weights).
//   pass 1: Gr,Gz = [x|h]@([Wr;Ur],[Wz;Uz]); z in regs; rh overwrites h planes
//   pass 2: Gh = [x|rh]@[Wh;Uh]; out = z*h + (1-z)*tanh(Gh+bh)
#define HID   256
#define MT    32
#define PL    128        // uints per A-plane row (512B rows)
#define KCH   32         // k16 chunks over stacked K=512

// fragment-order weight scratch: [entry][warp][lane][16 uints (8 hi + 8 lo)]
// pass1 entries: kc*2 + {0=r,1=z};  pass2 entries: kc (gate h)
__device__ unsigned wfp1[64][8][32][16];   // 1MB
__device__ unsigned wfp2[32][8][32][16];   // 512KB

__device__ __forceinline__ unsigned sm32(const void* p) {
    return (unsigned)__cvta_generic_to_shared(p);
}
#define LDSM4(R0,R1,R2,R3,A) \
    asm volatile("ldmatrix.sync.aligned.m8n8.x4.shared.b16 {%0,%1,%2,%3}, [%4];" \
        : "=r"(R0), "=r"(R1), "=r"(R2), "=r"(R3) : "r"(A))

__device__ __forceinline__ void bsplit(float x0, float x1, unsigned& hi, unsigned& lo) {
    asm("cvt.rn.bf16x2.f32 %0, %1, %2;" : "=r"(hi) : "f"(x1), "f"(x0));
    float h0 = __uint_as_float(hi << 16);
    float h1 = __uint_as_float(hi & 0xffff0000u);
    asm("cvt.rn.bf16x2.f32 %0, %1, %2;" : "=r"(lo) : "f"(x1 - h1), "f"(x0 - h0));
}
__device__ __forceinline__ float2 brecon(unsigned hi, unsigned lo) {
    float2 v;
    v.x = __uint_as_float(hi << 16) + __uint_as_float(lo << 16);
    v.y = __uint_as_float(hi & 0xffff0000u) + __uint_as_float(lo & 0xffff0000u);
    return v;
}
__device__ __forceinline__ void mma16(float c[4], const unsigned a[4], const unsigned b[2]) {
    asm volatile(
        "mma.sync.aligned.m16n8k16.row.col.f32.bf16.bf16.f32 "
        "{%0,%1,%2,%3}, {%4,%5,%6,%7}, {%8,%9}, {%0,%1,%2,%3};\n"
        : "+f"(c[0]), "+f"(c[1]), "+f"(c[2]), "+f"(c[3])
        : "r"(a[0]), "r"(a[1]), "r"(a[2]), "r"(a[3]), "r"(b[0]), "r"(b[1]));
}
__device__ __forceinline__ void mma3(float c[4],
                                     const unsigned ahi[4], const unsigned alo[4],
                                     const unsigned bhi[2], const unsigned blo[2]) {
    mma16(c, alo, bhi);
    mma16(c, ahi, blo);
    mma16(c, ahi, bhi);
}
__device__ __forceinline__ float sigf(float v) { return 1.0f / (1.0f + __expf(-v)); }

// ---------------- prologue: write weights in mma B-fragment order ----------------
// PTX m16n8k16 B frag (row.col): lane l: b0 = {B[k][n],B[k+1][n]} k=(l%4)*2, n=l/4;
// b1 = same at k+8.  frag[nt*2+q] = hi-plane uint for n-block nt, k-half q; +8 = lo.
__global__ void __launch_bounds__(256)
gru_split_w(const float* __restrict__ Wz, const float* __restrict__ Uz,
            const float* __restrict__ Wr, const float* __restrict__ Ur,
            const float* __restrict__ Wh, const float* __restrict__ Uh)
{
    int b = blockIdx.x, t = threadIdx.x, w = t >> 5, l = t & 31;
    const float *W, *U;
    unsigned* dst;
    int kc;
    if (b < 64) {
        kc = b >> 1;
        int gs = b & 1;                 // 0=r, 1=z (pass-1 entry interleave)
        W = gs ? Wz : Wr;
        U = gs ? Uz : Ur;
        dst = wfp1[b][w][l];
    } else {
        kc = b - 64;
        W = Wh; U = Uh;
        dst = wfp2[kc][w][l];
    }
    unsigned fr[16];
    #pragma unroll
    for (int nt = 0; nt < 4; ++nt)
        #pragma unroll
        for (int q = 0; q < 2; ++q) {
            int n = w * 32 + nt * 8 + (l >> 2);
            int k = kc * 16 + (l & 3) * 2 + q * 8;     // even; k,k+1 same half
            const float* s = (k < HID) ? (W + (size_t)k * HID) : (U + (size_t)(k - HID) * HID);
            bsplit(s[n], s[HID + n], fr[nt * 2 + q], fr[8 + nt * 2 + q]);
        }
    *(uint4*)(dst)      = make_uint4(fr[0],  fr[1],  fr[2],  fr[3]);
    *(uint4*)(dst + 4)  = make_uint4(fr[4],  fr[5],  fr[6],  fr[7]);
    *(uint4*)(dst + 8)  = make_uint4(fr[8],  fr[9],  fr[10], fr[11]);
    *(uint4*)(dst + 12) = make_uint4(fr[12], fr[13], fr[14], fr[15]);
}

// ---------------- main fused kernel ----------------
__global__ void __launch_bounds__(256, 2)
gru_fused3(const float* __restrict__ x,  const float* __restrict__ h,
           const float* __restrict__ bz, const float* __restrict__ br,
           const float* __restrict__ bh,
           float* __restrict__ out, float* __restrict__ out2, int rows)
{
    extern __shared__ unsigned smem_u[];
    unsigned* xhi = smem_u;              // 32 x 128 uints each (16KB)
    unsigned* xlo = xhi + MT * PL;
    unsigned* hhi = xlo + MT * PL;       // holds h, then rh
    unsigned* hlo = hhi + MT * PL;

    const int tid  = threadIdx.x;
    const int lane = tid & 31;
    const int warp = tid >> 5;
    const int tg   = lane >> 2;
    const int tq   = lane & 3;
    const int n0w  = warp * 32;
    const int row0 = blockIdx.x * MT;

    const unsigned xhiA = sm32(xhi), xloA = sm32(xlo);
    const unsigned hhiA = sm32(hhi), hloA = sm32(hlo);

    // ---- stage x/h into split packed swizzled planes ----
    #pragma unroll
    for (int i = tid; i < MT * 64; i += 256) {
        int r  = i >> 6;
        int c4 = (i & 63) << 2;
        int gr = row0 + r;
        float4 vx = make_float4(0.f, 0.f, 0.f, 0.f), vh = vx;
        if (gr < rows) {
            vx = *(const float4*)(x + (size_t)gr * HID + c4);
            vh = *(const float4*)(h + (size_t)gr * HID + c4);
        }
        int sw = (r & 7) << 2;
        int p0 = (c4 >> 1) ^ sw;
        int p1 = ((c4 >> 1) + 1) ^ sw;
        unsigned hi, lo;
        bsplit(vx.x, vx.y, hi, lo); xhi[r * PL + p0] = hi; xlo[r * PL + p0] = lo;
        bsplit(vx.z, vx.w, hi, lo); xhi[r * PL + p1] = hi; xlo[r * PL + p1] = lo;
        bsplit(vh.x, vh.y, hi, lo); hhi[r * PL + p0] = hi; hlo[r * PL + p0] = lo;
        bsplit(vh.z, vh.w, hi, lo); hhi[r * PL + p1] = hi; hlo[r * PL + p1] = lo;
    }
    __syncthreads();

    // ldmatrix lane geometry (A only)
    const int aRowOff = (lane & 7) + ((lane >> 3) & 1) * 8;
    const int aUsel   = (lane >> 4) & 1;

    auto load_a = [&](unsigned ahi[2][4], unsigned alo[2][4],
                      unsigned PhiA, unsigned PloA, int uBase) {
        #pragma unroll
        for (int mt = 0; mt < 2; ++mt) {
            int rowA = mt * 16 + aRowOff;
            unsigned swu = (unsigned)(((uBase + aUsel) ^ (rowA & 7)) << 4);
            unsigned byteOff = (unsigned)rowA * 512u + swu;
            LDSM4(ahi[mt][0], ahi[mt][1], ahi[mt][2], ahi[mt][3], PhiA + byteOff);
            LDSM4(alo[mt][0], alo[mt][1], alo[mt][2], alo[mt][3], PloA + byteOff);
        }
    };
    // load one 64B B-fragment bundle straight to registers
    auto ldB = [&](unsigned f[16], const unsigned* p) {
        uint4 v0 = __ldg((const uint4*)p);
        uint4 v1 = __ldg((const uint4*)(p + 4));
        uint4 v2 = __ldg((const uint4*)(p + 8));
        uint4 v3 = __ldg((const uint4*)(p + 12));
        f[0]=v0.x; f[1]=v0.y; f[2]=v0.z;  f[3]=v0.w;
        f[4]=v1.x; f[5]=v1.y; f[6]=v1.z;  f[7]=v1.w;
        f[8]=v2.x; f[9]=v2.y; f[10]=v2.z; f[11]=v2.w;
        f[12]=v3.x; f[13]=v3.y; f[14]=v3.z; f[15]=v3.w;
    };
    auto mmaB = [&](float c[2][4][4], unsigned ahi[2][4], unsigned alo[2][4],
                    const unsigned f[16]) {
        #pragma unroll
        for (int mt = 0; mt < 2; ++mt)
            #pragma unroll
            for (int nt = 0; nt < 4; ++nt)
                mma3(c[mt][nt], ahi[mt], alo[mt], &f[nt * 2], &f[8 + nt * 2]);
    };

    float cr[2][4][4], cz[2][4][4];
    #pragma unroll
    for (int i = 0; i < 2; ++i)
        #pragma unroll
        for (int j = 0; j < 4; ++j)
            #pragma unroll
            for (int q = 0; q < 4; ++q) { cr[i][j][q] = 0.f; cz[i][j][q] = 0.f; }

    unsigned ahi[2][4], alo[2][4], fA[16], fB[16];

    // ============ pass 1: Gr + Gz over [x|h] (r/z entries share A) ============
    {
        const unsigned* wp = &wfp1[0][warp][lane][0];   // entry stride: 4096 uints
        ldB(fA, wp);                                    // r, kc=0
        for (int kc = 0; kc < KCH; ++kc) {
            ldB(fB, wp + 4096);                         // z entry for this kc
            unsigned PhiA = (kc < 16) ? xhiA : hhiA;
            unsigned PloA = (kc < 16) ? xloA : hloA;
            load_a(ahi, alo, PhiA, PloA, (kc & 15) * 2);
            mmaB(cr, ahi, alo, fA);
            wp += 8192;
            if (kc + 1 < KCH) ldB(fA, wp);              // r entry for kc+1
            mmaB(cz, ahi, alo, fB);
        }
    }
    __syncthreads();   // all warps done reading h planes before rh overwrite

    // ============ epilogue 1: z in regs; rh = sigmoid(Gr+br)*h overwrites h planes
    float zreg[2][4][4];
    #pragma unroll
    for (int nt = 0; nt < 4; ++nt) {
        int colg = n0w + nt * 8 + 2 * tq;
        int kp   = colg >> 1;
        float br0 = __ldg(br + colg), br1 = __ldg(br + colg + 1);
        float bz0 = __ldg(bz + colg), bz1 = __ldg(bz + colg + 1);
        #pragma unroll
        for (int mt = 0; mt < 2; ++mt) {
            int r0 = mt * 16 + tg, r1 = r0 + 8;
            int pos = kp ^ (tg << 2);
            float2 hv0 = brecon(hhi[r0 * PL + pos], hlo[r0 * PL + pos]);
            float2 hv1 = brecon(hhi[r1 * PL + pos], hlo[r1 * PL + pos]);
            zreg[mt][nt][0] = sigf(cz[mt][nt][0] + bz0);
            zreg[mt][nt][1] = sigf(cz[mt][nt][1] + bz1);
            zreg[mt][nt][2] = sigf(cz[mt][nt][2] + bz0);
            zreg[mt][nt][3] = sigf(cz[mt][nt][3] + bz1);
            float v00 = sigf(cr[mt][nt][0] + br0) * hv0.x;
            float v01 = sigf(cr[mt][nt][1] + br1) * hv0.y;
            float v10 = sigf(cr[mt][nt][2] + br0) * hv1.x;
            float v11 = sigf(cr[mt][nt][3] + br1) * hv1.y;
            unsigned hi, lo;
            bsplit(v00, v01, hi, lo); hhi[r0 * PL + pos] = hi; hlo[r0 * PL + pos] = lo;
            bsplit(v10, v11, hi, lo); hhi[r1 * PL + pos] = hi; hlo[r1 * PL + pos] = lo;
        }
    }
    __syncthreads();

    // ============ pass 2: Gh over [x|rh] ============
    float ch[2][4][4];
    #pragma unroll
    for (int i = 0; i < 2; ++i)
        #pragma unroll
        for (int j = 0; j < 4; ++j)
            #pragma unroll
            for (int q = 0; q < 4; ++q) ch[i][j][q] = 0.f;
    {
        const unsigned* wp2 = &wfp2[0][warp][lane][0];
        ldB(fA, wp2);
        for (int kc = 0; kc < KCH; kc += 2) {
            unsigned PhiA = (kc < 16) ? xhiA : hhiA;
            unsigned PloA = (kc < 16) ? xloA : hloA;
            ldB(fB, wp2 + 4096);
            load_a(ahi, alo, PhiA, PloA, (kc & 15) * 2);
            mmaB(ch, ahi, alo, fA);
            int k1 = kc + 1;
            unsigned Phi1 = (k1 < 16) ? xhiA : hhiA;
            unsigned Plo1 = (k1 < 16) ? xloA : hloA;
            if (kc + 2 < KCH) ldB(fA, wp2 + 8192);
            load_a(ahi, alo, Phi1, Plo1, (k1 & 15) * 2);
            mmaB(ch, ahi, alo, fB);
            wp2 += 8192;
        }
    }

    // ============ final blend: out = z*h + (1-z)*tanh(Gh+bh), h from gmem ============
    #pragma unroll
    for (int nt = 0; nt < 4; ++nt) {
        int colg = n0w + nt * 8 + 2 * tq;
        float b0 = __ldg(bh + colg), b1 = __ldg(bh + colg + 1);
        #pragma unroll
        for (int mt = 0; mt < 2; ++mt) {
            int r0 = mt * 16 + tg, r1 = r0 + 8;
            int gr0 = row0 + r0, gr1 = row0 + r1;
            if (gr0 < rows) {
                float2 hv = *(const float2*)(h + (size_t)gr0 * HID + colg);
                float z0 = zreg[mt][nt][0], z1 = zreg[mt][nt][1];
                float t0 = tanhf(ch[mt][nt][0] + b0);
                float t1 = tanhf(ch[mt][nt][1] + b1);
                float o0 = z0 * hv.x + (1.f - z0) * t0;
                float o1 = z1 * hv.y + (1.f - z1) * t1;
                *(float2*)(out + (size_t)gr0 * HID + colg) = make_float2(o0, o1);
                if (out2) *(float2*)(out2 + (size_t)gr0 * HID + colg) = make_float2(o0, o1);
            }
            if (gr1 < rows) {
                float2 hv = *(const float2*)(h + (size_t)gr1 * HID + colg);
                float z0 = zreg[mt][nt][2], z1 = zreg[mt][nt][3];
                float t0 = tanhf(ch[mt][nt][2] + b0);
                float t1 = tanhf(ch[mt][nt][3] + b1);
                float o0 = z0 * hv.x + (1.f - z0) * t0;
                float o1 = z1 * hv.y + (1.f - z1) * t1;
                *(float2*)(out + (size_t)gr1 * HID + colg) = make_float2(o0, o1);
                if (out2) *(float2*)(out2 + (size_t)gr1 * HID + colg) = make_float2(o0, o1);
            }
        }
    }
}

extern "C" void kernel_launch(void* const* d_in, const int* in_sizes, int n_in,
                              void* d_out, int out_size) {
    const float* x  = (const float*)d_in[0];
    const float* h  = (const float*)d_in[1];
    const float* Wz = (const float*)d_in[2];
    const float* Uz = (const float*)d_in[3];
    const float* bz = (const float*)d_in[4];
    const float* Wr = (const float*)d_in[5];
    const float* Ur = (const float*)d_in[6];
    const float* br = (const float*)d_in[7];
    const float* Wh = (const float*)d_in[8];
    const float* Uh = (const float*)d_in[9];
    const float* bh = (const float*)d_in[10];
    (void)n_in;

    int rows = in_sizes[0] / HID;
    float* out  = (float*)d_out;
    float* out2 = ((long long)out_size >= 2LL * rows * HID) ? out + (size_t)rows * HID : nullptr;

    gru_split_w<<<96, 256>>>(Wz, Uz, Wr, Ur, Wh, Uh);

    const int smem_bytes = 4 * MT * PL * (int)sizeof(unsigned);   // 65536
    cudaFuncSetAttribute(gru_fused3, cudaFuncAttributeMaxDynamicSharedMemorySize, smem_bytes);

    int grid = (rows + MT - 1) / MT;
    gru_fused3<<<grid, 256, smem_bytes>>>(x, h, bz, br, bh, out, out2, rows);
}

// round 14
// speedup vs baseline: 1.4132x; 1.4132x over previous
#include <cuda_runtime.h>
#include <cstdint>

// Fused GRU cell — bf16 hi/lo split (3 MMAs), mma.sync + ldmatrix, 2 CTA/SM,
// warp-private weight pipeline (cp.async.cg), r+z fused pass, FULLY UNROLLED
// hot loops (all slot/pointer arithmetic folded to immediates).
//   pass 1: Gr,Gz = [x|h]@([Wr;Ur],[Wz;Uz]); z in regs; rh overwrites h planes
//   pass 2: Gh = [x|rh]@[Wh;Uh]; out = z*h + (1-z)*tanh(Gh+bh)  (h from gmem)
#define HID   256
#define MT    32
#define PL    128        // uints per A-plane row (512B rows)
#define KCH   32         // k16 chunks over stacked K=512
#define BLOBU 2048       // uints per B chunk blob (8KB)
#define NSLOT 3
#define SLOTU 4096       // uints per slot (8 warps x 2KB)

// ldmatrix-native B scratch: [gate z/r/h][plane hi/lo][kc][npair16][mat4][row8][4xuint]
__device__ unsigned wsc[3][2][KCH][BLOBU];

__device__ __forceinline__ unsigned sm32(const void* p) {
    return (unsigned)__cvta_generic_to_shared(p);
}
__device__ __forceinline__ void cp16(unsigned s, const void* g) {
    asm volatile("cp.async.cg.shared.global [%0], [%1], 16;\n" :: "r"(s), "l"(g));
}
__device__ __forceinline__ void cp_commit() { asm volatile("cp.async.commit_group;\n"); }
__device__ __forceinline__ void cp_waitg1() { asm volatile("cp.async.wait_group 1;\n" ::: "memory"); }

#define LDSM4(R0,R1,R2,R3,A) \
    asm volatile("ldmatrix.sync.aligned.m8n8.x4.shared.b16 {%0,%1,%2,%3}, [%4];" \
        : "=r"(R0), "=r"(R1), "=r"(R2), "=r"(R3) : "r"(A))

__device__ __forceinline__ void bsplit(float x0, float x1, unsigned& hi, unsigned& lo) {
    asm("cvt.rn.bf16x2.f32 %0, %1, %2;" : "=r"(hi) : "f"(x1), "f"(x0));
    float h0 = __uint_as_float(hi << 16);
    float h1 = __uint_as_float(hi & 0xffff0000u);
    asm("cvt.rn.bf16x2.f32 %0, %1, %2;" : "=r"(lo) : "f"(x1 - h1), "f"(x0 - h0));
}
__device__ __forceinline__ float2 brecon(unsigned hi, unsigned lo) {
    float2 v;
    v.x = __uint_as_float(hi << 16) + __uint_as_float(lo << 16);
    v.y = __uint_as_float(hi & 0xffff0000u) + __uint_as_float(lo & 0xffff0000u);
    return v;
}
__device__ __forceinline__ void mma16(float c[4], const unsigned a[4], const unsigned b[2]) {
    asm volatile(
        "mma.sync.aligned.m16n8k16.row.col.f32.bf16.bf16.f32 "
        "{%0,%1,%2,%3}, {%4,%5,%6,%7}, {%8,%9}, {%0,%1,%2,%3};\n"
        : "+f"(c[0]), "+f"(c[1]), "+f"(c[2]), "+f"(c[3])
        : "r"(a[0]), "r"(a[1]), "r"(a[2]), "r"(a[3]), "r"(b[0]), "r"(b[1]));
}
__device__ __forceinline__ void mma3(float c[4],
                                     const unsigned ahi[4], const unsigned alo[4],
                                     const unsigned bhi[2], const unsigned blo[2]) {
    mma16(c, alo, bhi);
    mma16(c, ahi, blo);
    mma16(c, ahi, bhi);
}
__device__ __forceinline__ float sigf(float v) { return 1.0f / (1.0f + __expf(-v)); }

// ---------------- prologue: split weights into ldmatrix-tiled bf16 hi/lo scratch ------
__global__ void __launch_bounds__(256)
gru_split_w(const float* __restrict__ Wz, const float* __restrict__ Uz,
            const float* __restrict__ Wr, const float* __restrict__ Ur,
            const float* __restrict__ Wh, const float* __restrict__ Uh)
{
    int g  = blockIdx.x >> 5;        // gate 0=z,1=r,2=h
    int kc = blockIdx.x & 31;        // k16 chunk in stacked K
    int n  = threadIdx.x;            // 0..255
    const float* W = (g == 0) ? Wz : (g == 1) ? Wr : Wh;
    const float* U = (g == 0) ? Uz : (g == 1) ? Ur : Uh;
    float v[16];
    #pragma unroll
    for (int k = 0; k < 16; ++k) {
        int kg = kc * 16 + k;
        const float* src = (kg < HID) ? (W + (size_t)kg * HID) : (U + (size_t)(kg - HID) * HID);
        v[k] = src[n];
    }
    int npair = n >> 4, j = n & 7, msel = (n >> 3) & 1;
    unsigned base = npair * 128 + msel * 64 + j * 4;
    #pragma unroll
    for (int usel = 0; usel < 2; ++usel) {
        unsigned h4[4], l4[4];
        #pragma unroll
        for (int q = 0; q < 4; ++q) {
            int kp = usel * 4 + q;
            bsplit(v[2 * kp], v[2 * kp + 1], h4[q], l4[q]);
        }
        unsigned off = base + usel * 32;
        *(uint4*)&wsc[g][0][kc][off] = make_uint4(h4[0], h4[1], h4[2], h4[3]);
        *(uint4*)&wsc[g][1][kc][off] = make_uint4(l4[0], l4[1], l4[2], l4[3]);
    }
}

// ---------------- main fused kernel ----------------
__global__ void __launch_bounds__(256, 2)
gru_fused3(const float* __restrict__ x,  const float* __restrict__ h,
           const float* __restrict__ bz, const float* __restrict__ br,
           const float* __restrict__ bh,
           float* __restrict__ out, float* __restrict__ out2, int rows)
{
    extern __shared__ unsigned smem_u[];
    unsigned* xhi = smem_u;              // 32 x 128 uints each (16KB)
    unsigned* xlo = xhi + MT * PL;
    unsigned* hhi = xlo + MT * PL;       // holds h, then rh
    unsigned* hlo = hhi + MT * PL;
    unsigned* wb  = hlo + MT * PL;       // NSLOT slots x 4096 uints

    const int tid  = threadIdx.x;
    const int lane = tid & 31;
    const int warp = tid >> 5;
    const int tg   = lane >> 2;
    const int tq   = lane & 3;
    const int n0w  = warp * 32;
    const int row0 = blockIdx.x * MT;

    const unsigned xhiA = sm32(xhi), xloA = sm32(xlo);
    const unsigned hhiA = sm32(hhi), hloA = sm32(hlo);
    const unsigned wbA  = sm32(wb);
    const unsigned wslice = wbA + (unsigned)warp * 2048;

    // ---- stage x/h into split packed swizzled planes ----
    #pragma unroll
    for (int i = tid; i < MT * 64; i += 256) {
        int r  = i >> 6;
        int c4 = (i & 63) << 2;
        int gr = row0 + r;
        float4 vx = make_float4(0.f, 0.f, 0.f, 0.f), vh = vx;
        if (gr < rows) {
            vx = *(const float4*)(x + (size_t)gr * HID + c4);
            vh = *(const float4*)(h + (size_t)gr * HID + c4);
        }
        int sw = (r & 7) << 2;
        int p0 = (c4 >> 1) ^ sw;
        int p1 = ((c4 >> 1) + 1) ^ sw;
        unsigned hi, lo;
        bsplit(vx.x, vx.y, hi, lo); xhi[r * PL + p0] = hi; xlo[r * PL + p0] = lo;
        bsplit(vx.z, vx.w, hi, lo); xhi[r * PL + p1] = hi; xlo[r * PL + p1] = lo;
        bsplit(vh.x, vh.y, hi, lo); hhi[r * PL + p0] = hi; hlo[r * PL + p0] = lo;
        bsplit(vh.z, vh.w, hi, lo); hhi[r * PL + p1] = hi; hlo[r * PL + p1] = lo;
    }
    __syncthreads();

    // warp-private copy of this warp's 2KB slice (hi 1KB + lo 1KB) of chunk kc
    auto pfw = [&](int gate, int kc, int slot) {
        const unsigned* srcHi = &wsc[gate][0][kc][warp * 256];
        const unsigned* srcLo = &wsc[gate][1][kc][warp * 256];
        unsigned dst = wslice + (unsigned)slot * 16384;
        cp16(dst + lane * 16,        srcHi + lane * 4);
        cp16(dst + 512 + lane * 16,  srcHi + 128 + lane * 4);
        cp16(dst + 1024 + lane * 16, srcLo + lane * 4);
        cp16(dst + 1536 + lane * 16, srcLo + 128 + lane * 4);
    };

    // ldmatrix lane geometry
    const int aRowOff = (lane & 7) + ((lane >> 3) & 1) * 8;
    const int aUsel   = (lane >> 4) & 1;
    const unsigned bOff = (unsigned)((lane >> 3) * 128 + (lane & 7) * 16);

    auto load_a = [&](unsigned ahi[2][4], unsigned alo[2][4],
                      unsigned PhiA, unsigned PloA, int uBase) {
        #pragma unroll
        for (int mt = 0; mt < 2; ++mt) {
            int rowA = mt * 16 + aRowOff;
            unsigned swu = (unsigned)(((uBase + aUsel) ^ (rowA & 7)) << 4);
            unsigned byteOff = (unsigned)rowA * 512u + swu;
            LDSM4(alo[mt][0], alo[mt][1], alo[mt][2], alo[mt][3], PloA + byteOff);
            LDSM4(ahi[mt][0], ahi[mt][1], ahi[mt][2], ahi[mt][3], PhiA + byteOff);
        }
    };
    auto load_b = [&](unsigned bf[4][2], unsigned base) {
        LDSM4(bf[0][0], bf[0][1], bf[1][0], bf[1][1], base + bOff);
        LDSM4(bf[2][0], bf[2][1], bf[3][0], bf[3][1], base + 512 + bOff);
    };

    float cr[2][4][4], cz[2][4][4];
    #pragma unroll
    for (int i = 0; i < 2; ++i)
        #pragma unroll
        for (int j = 0; j < 4; ++j)
            #pragma unroll
            for (int q = 0; q < 4; ++q) { cr[i][j][q] = 0.f; cz[i][j][q] = 0.f; }

    // ============ pass 1: Gr + Gz over [x|h], interleaved entries (FULL UNROLL) ========
    {
        pfw(1, 0, 0); cp_commit();      // entry 0: gate r chunk 0
        pfw(0, 0, 1); cp_commit();      // entry 1: gate z chunk 0
        unsigned ahi[2][4], alo[2][4];
        #pragma unroll
        for (int e = 0; e < 2 * KCH; ++e) {
            const int slot = e % NSLOT;
            cp_waitg1();
            __syncwarp();
            const int en = e + 2;
            if (en < 2 * KCH) pfw((en & 1) ? 0 : 1, en >> 1, en % NSLOT);
            cp_commit();
            const int kc = e >> 1;
            if ((e & 1) == 0) {
                unsigned PhiA = (kc < 16) ? xhiA : hhiA;
                unsigned PloA = (kc < 16) ? xloA : hloA;
                load_a(ahi, alo, PhiA, PloA, (kc & 15) * 2);
            }
            unsigned bhi[4][2], blo[4][2];
            unsigned base = wslice + (unsigned)slot * 16384;
            load_b(bhi, base);
            load_b(blo, base + 1024);
            #pragma unroll
            for (int mt = 0; mt < 2; ++mt)
                #pragma unroll
                for (int nt = 0; nt < 4; ++nt)
                    mma3((e & 1) ? cz[mt][nt] : cr[mt][nt], ahi[mt], alo[mt], bhi[nt], blo[nt]);
        }
        __syncthreads();
    }

    // ============ epilogue 1: z in regs; rh = sigmoid(Gr+br)*h overwrites h planes
    float zreg[2][4][4];
    #pragma unroll
    for (int nt = 0; nt < 4; ++nt) {
        int colg = n0w + nt * 8 + 2 * tq;
        int kp   = colg >> 1;
        float br0 = __ldg(br + colg), br1 = __ldg(br + colg + 1);
        float bz0 = __ldg(bz + colg), bz1 = __ldg(bz + colg + 1);
        #pragma unroll
        for (int mt = 0; mt < 2; ++mt) {
            int r0 = mt * 16 + tg, r1 = r0 + 8;
            int pos = kp ^ (tg << 2);
            float2 hv0 = brecon(hhi[r0 * PL + pos], hlo[r0 * PL + pos]);
            float2 hv1 = brecon(hhi[r1 * PL + pos], hlo[r1 * PL + pos]);
            zreg[mt][nt][0] = sigf(cz[mt][nt][0] + bz0);
            zreg[mt][nt][1] = sigf(cz[mt][nt][1] + bz1);
            zreg[mt][nt][2] = sigf(cz[mt][nt][2] + bz0);
            zreg[mt][nt][3] = sigf(cz[mt][nt][3] + bz1);
            float v00 = sigf(cr[mt][nt][0] + br0) * hv0.x;
            float v01 = sigf(cr[mt][nt][1] + br1) * hv0.y;
            float v10 = sigf(cr[mt][nt][2] + br0) * hv1.x;
            float v11 = sigf(cr[mt][nt][3] + br1) * hv1.y;
            unsigned hi, lo;
            bsplit(v00, v01, hi, lo); hhi[r0 * PL + pos] = hi; hlo[r0 * PL + pos] = lo;
            bsplit(v10, v11, hi, lo); hhi[r1 * PL + pos] = hi; hlo[r1 * PL + pos] = lo;
        }
    }
    __syncthreads();

    // ============ pass 2: Gh over [x|rh] (FULL UNROLL) ============
    float ch[2][4][4];
    #pragma unroll
    for (int i = 0; i < 2; ++i)
        #pragma unroll
        for (int j = 0; j < 4; ++j)
            #pragma unroll
            for (int q = 0; q < 4; ++q) ch[i][j][q] = 0.f;
    {
        pfw(2, 0, 0); cp_commit();
        pfw(2, 1, 1); cp_commit();
        #pragma unroll
        for (int kc = 0; kc < KCH; ++kc) {
            const int slot = kc % NSLOT;
            cp_waitg1();
            __syncwarp();
            if (kc + 2 < KCH) pfw(2, kc + 2, (kc + 2) % NSLOT);
            cp_commit();
            unsigned PhiA = (kc < 16) ? xhiA : hhiA;
            unsigned PloA = (kc < 16) ? xloA : hloA;
            unsigned ahi[2][4], alo[2][4], bhi[4][2], blo[4][2];
            load_a(ahi, alo, PhiA, PloA, (kc & 15) * 2);
            unsigned base = wslice + (unsigned)slot * 16384;
            load_b(bhi, base);
            load_b(blo, base + 1024);
            #pragma unroll
            for (int mt = 0; mt < 2; ++mt)
                #pragma unroll
                for (int nt = 0; nt < 4; ++nt)
                    mma3(ch[mt][nt], ahi[mt], alo[mt], bhi[nt], blo[nt]);
        }
    }

    // ============ final blend: out = z*h + (1-z)*tanh(Gh+bh), h from gmem ============
    #pragma unroll
    for (int nt = 0; nt < 4; ++nt) {
        int colg = n0w + nt * 8 + 2 * tq;
        float b0 = __ldg(bh + colg), b1 = __ldg(bh + colg + 1);
        #pragma unroll
        for (int mt = 0; mt < 2; ++mt) {
            int r0 = mt * 16 + tg, r1 = r0 + 8;
            int gr0 = row0 + r0, gr1 = row0 + r1;
            if (gr0 < rows) {
                float2 hv = *(const float2*)(h + (size_t)gr0 * HID + colg);
                float z0 = zreg[mt][nt][0], z1 = zreg[mt][nt][1];
                float t0 = tanhf(ch[mt][nt][0] + b0);
                float t1 = tanhf(ch[mt][nt][1] + b1);
                float o0 = z0 * hv.x + (1.f - z0) * t0;
                float o1 = z1 * hv.y + (1.f - z1) * t1;
                *(float2*)(out + (size_t)gr0 * HID + colg) = make_float2(o0, o1);
                if (out2) *(float2*)(out2 + (size_t)gr0 * HID + colg) = make_float2(o0, o1);
            }
            if (gr1 < rows) {
                float2 hv = *(const float2*)(h + (size_t)gr1 * HID + colg);
                float z0 = zreg[mt][nt][2], z1 = zreg[mt][nt][3];
                float t0 = tanhf(ch[mt][nt][2] + b0);
                float t1 = tanhf(ch[mt][nt][3] + b1);
                float o0 = z0 * hv.x + (1.f - z0) * t0;
                float o1 = z1 * hv.y + (1.f - z1) * t1;
                *(float2*)(out + (size_t)gr1 * HID + colg) = make_float2(o0, o1);
                if (out2) *(float2*)(out2 + (size_t)gr1 * HID + colg) = make_float2(o0, o1);
            }
        }
    }
}

extern "C" void kernel_launch(void* const* d_in, const int* in_sizes, int n_in,
                              void* d_out, int out_size) {
    const float* x  = (const float*)d_in[0];
    const float* h  = (const float*)d_in[1];
    const float* Wz = (const float*)d_in[2];
    const float* Uz = (const float*)d_in[3];
    const float* bz = (const float*)d_in[4];
    const float* Wr = (const float*)d_in[5];
    const float* Ur = (const float*)d_in[6];
    const float* br = (const float*)d_in[7];
    const float* Wh = (const float*)d_in[8];
    const float* Uh = (const float*)d_in[9];
    const float* bh = (const float*)d_in[10];
    (void)n_in;

    int rows = in_sizes[0] / HID;
    float* out  = (float*)d_out;
    float* out2 = ((long long)out_size >= 2LL * rows * HID) ? out + (size_t)rows * HID : nullptr;

    gru_split_w<<<96, 256>>>(Wz, Uz, Wr, Ur, Wh, Uh);

    const int smem_bytes = (4 * MT * PL + NSLOT * SLOTU) * (int)sizeof(unsigned); // 114688
    cudaFuncSetAttribute(gru_fused3, cudaFuncAttributeMaxDynamicSharedMemorySize, smem_bytes);

    int grid = (rows + MT - 1) / MT;
    gru_fused3<<<grid, 256, smem_bytes>>>(x, h, bz, br, bh, out, out2, rows);
}